// round 10
// baseline (speedup 1.0000x reference)
#include <cuda_runtime.h>
#include <stdint.h>
#include <math.h>

#define NB 4096
#define DD 1024          // per-tensor dim (K total = 2048)
#define NE 64
#define MT 32            // tokens per CTA
#define NCTA (NB / MT)   // 128
#define NT 256
#define NCHUNK 32        // K chunks of 64

// smem layout (bytes). Each K element is a uint2 {tf32_hi, tf32_lo} = 8B.
#define ROWB 544                  // row stride: 64*8 pad-> 544 (half-warp conflict-free)
#define XS_BUF (32 * ROWB)        // 17408
#define GS_BUF (64 * ROWB)        // 34816
#define XS0 0
#define GS0 (2 * XS_BUF)          // 34816
#define VS0 (GS0 + 2 * GS_BUF)    // 104448
#define VROWB 272                 // 68 floats
#define SMEM_BYTES (VS0 + 32 * VROWB + 512)

// Scratch: pre-split gate weights (hi,lo tf32) + expert norms
__device__ uint2 g_g2[NE * 2048];
__device__ float g_gn[NE];

static __device__ __forceinline__ uint32_t f2tf(float x) {
    uint32_t r;
    asm("cvt.rna.tf32.f32 %0, %1;" : "=r"(r) : "f"(x));
    return r;
}
static __device__ __forceinline__ uint32_t s2u(const void* p) {
    uint32_t r;
    asm("{ .reg .u64 t; cvta.to.shared.u64 t, %1; cvt.u32.u64 %0, t; }"
        : "=r"(r) : "l"(p));
    return r;
}
static __device__ __forceinline__ void mma_tf32(float* c, uint32_t a0, uint32_t a1,
                                                uint32_t a2, uint32_t a3,
                                                uint32_t b0, uint32_t b1) {
    asm volatile(
        "mma.sync.aligned.m16n8k8.row.col.f32.tf32.tf32.f32 "
        "{%0,%1,%2,%3}, {%4,%5,%6,%7}, {%8,%9}, {%0,%1,%2,%3};"
        : "+f"(c[0]), "+f"(c[1]), "+f"(c[2]), "+f"(c[3])
        : "r"(a0), "r"(a1), "r"(a2), "r"(a3), "r"(b0), "r"(b1));
}
#define CP16(dst, src) \
    asm volatile("cp.async.cg.shared.global [%0], [%1], 16;" \
                 :: "r"(dst), "l"(src) : "memory")
#define CPCOMMIT() asm volatile("cp.async.commit_group;" ::: "memory")
#define CPWAIT0()  asm volatile("cp.async.wait_group 0;" ::: "memory")

// ---------------------------------------------------------------------------
// Prep: split gate weights into tf32 hi/lo, compute ||g_e||^2. 64 blocks.
// ---------------------------------------------------------------------------
__global__ __launch_bounds__(256) void prep_kernel(const float* __restrict__ gw) {
    const int e = blockIdx.x;
    const int tid = threadIdx.x;
    float s = 0.f;
#pragma unroll
    for (int i = 0; i < 8; i++) {
        int k = tid + i * 256;
        float v = gw[e * 2048 + k];
        uint32_t h = f2tf(v);
        float hf = __uint_as_float(h);
        uint32_t l = f2tf(v - hf);
        g_g2[e * 2048 + k] = make_uint2(h, l);
        s += v * v;
    }
#pragma unroll
    for (int o = 16; o; o >>= 1) s += __shfl_xor_sync(0xffffffffu, s, o);
    __shared__ float red[8];
    if ((tid & 31) == 0) red[tid >> 5] = s;
    __syncthreads();
    if (tid == 0) {
        float t = 0.f;
#pragma unroll
        for (int i = 0; i < 8; i++) t += red[i];
        g_gn[e] = t;
    }
}

// ---------------------------------------------------------------------------
// Fused GEMM (tf32 mma.sync, hi/lo split) + top-2 softmax scatter.
// 128 CTAs x 256 threads; M-tile 32, N = 64, K = 2048 in 32 chunks of 64.
// ---------------------------------------------------------------------------
__global__ __launch_bounds__(NT, 1)
void gating_mma(const float* __restrict__ t1, const float* __restrict__ t2,
                float* __restrict__ out) {
    extern __shared__ char sb[];
    const uint32_t sb32 = s2u(sb);

    const int tid = threadIdx.x;
    const int warp = tid >> 5;
    const int lane = tid & 31;
    const int t0 = blockIdx.x * MT;

    // warp tile: wm in {0,1} -> rows, wn in {0..3} -> 16 experts
    const int m0 = (warp >> 2) * 16;
    const int n0 = (warp & 3) * 16;

    // X conversion role: row = tid/8, k-slice s = tid%8 (8 floats per chunk)
    const int xrow = tid >> 3;
    const int xs = tid & 7;

    // G cp.async role: expert = tid/4, quarter q = tid%4 (16 uint2 per chunk)
    const int ge = tid >> 2;
    const int gq = tid & 3;

    float cH0[4] = {0, 0, 0, 0}, cL0[4] = {0, 0, 0, 0};
    float cH1[4] = {0, 0, 0, 0}, cL1[4] = {0, 0, 0, 0};
    float xsq = 0.f;

    // --- prologue: prefetch chunk 0 ---
    float4 xv0, xv1;
    {
        const float4* xsrc = (const float4*)t1;
        size_t base = (size_t)(t0 + xrow) * 256 + xs * 2;
        xv0 = xsrc[base];
        xv1 = xsrc[base + 1];
        uint32_t gdst = sb32 + GS0 + ge * ROWB + gq * 128;
        const uint2* gsrc = &g_g2[ge * 2048 + gq * 16];
#pragma unroll
        for (int i = 0; i < 8; i++) CP16(gdst + i * 16, (const void*)(gsrc + 2 * i));
        CPCOMMIT();
    }

    for (int c = 0; c < NCHUNK; c++) {
        const int b = c & 1;

        // 1) convert X regs -> smem (hi/lo tf32), accumulate ||x||^2
        {
            float v[8] = {xv0.x, xv0.y, xv0.z, xv0.w, xv1.x, xv1.y, xv1.z, xv1.w};
            uint4* dst = (uint4*)(sb + XS0 + b * XS_BUF + xrow * ROWB + xs * 64);
#pragma unroll
            for (int j = 0; j < 4; j++) {
                float v0 = v[2 * j], v1 = v[2 * j + 1];
                xsq += v0 * v0 + v1 * v1;
                uint32_t h0 = f2tf(v0), h1 = f2tf(v1);
                uint32_t l0 = f2tf(v0 - __uint_as_float(h0));
                uint32_t l1 = f2tf(v1 - __uint_as_float(h1));
                dst[j] = make_uint4(h0, l0, h1, l1);
            }
        }

        // 2) G chunk c arrived, 3) barrier
        CPWAIT0();
        __syncthreads();

        // 4) prefetch chunk c+1 (hides latency under MMA below)
        if (c + 1 < NCHUNK) {
            const int cn = c + 1;
            const float4* xsrc = (const float4*)((cn < 16) ? t1 : t2);
            size_t base = (size_t)(t0 + xrow) * 256 + (cn & 15) * 16 + xs * 2;
            xv0 = xsrc[base];
            xv1 = xsrc[base + 1];
            uint32_t gdst = sb32 + GS0 + (b ^ 1) * GS_BUF + ge * ROWB + gq * 128;
            const uint2* gsrc = &g_g2[ge * 2048 + cn * 64 + gq * 16];
#pragma unroll
            for (int i = 0; i < 8; i++) CP16(gdst + i * 16, (const void*)(gsrc + 2 * i));
            CPCOMMIT();
        }

        // 5) MMA over the 8 k-steps of chunk c
        const char* aB = sb + XS0 + b * XS_BUF + (m0 + (lane >> 2)) * ROWB + (lane & 3) * 8;
        const char* bB = sb + GS0 + b * GS_BUF + (n0 + (lane >> 2)) * ROWB + (lane & 3) * 8;
#pragma unroll
        for (int ks = 0; ks < 8; ks++) {
            uint2 A0 = *(const uint2*)(aB + ks * 64);
            uint2 A1 = *(const uint2*)(aB + ks * 64 + 8 * ROWB);
            uint2 A2 = *(const uint2*)(aB + ks * 64 + 32);
            uint2 A3 = *(const uint2*)(aB + ks * 64 + 8 * ROWB + 32);
            uint2 B00 = *(const uint2*)(bB + ks * 64);
            uint2 B01 = *(const uint2*)(bB + ks * 64 + 32);
            uint2 B10 = *(const uint2*)(bB + ks * 64 + 8 * ROWB);
            uint2 B11 = *(const uint2*)(bB + ks * 64 + 8 * ROWB + 32);
            // tile 0 (experts n0..n0+7): hi*hi into cH, cross terms into cL
            mma_tf32(cH0, A0.x, A1.x, A2.x, A3.x, B00.x, B01.x);
            mma_tf32(cL0, A0.x, A1.x, A2.x, A3.x, B00.y, B01.y);
            mma_tf32(cL0, A0.y, A1.y, A2.y, A3.y, B00.x, B01.x);
            // tile 1 (experts n0+8..n0+15)
            mma_tf32(cH1, A0.x, A1.x, A2.x, A3.x, B10.x, B11.x);
            mma_tf32(cL1, A0.x, A1.x, A2.x, A3.x, B10.y, B11.y);
            mma_tf32(cL1, A0.y, A1.y, A2.y, A3.y, B10.x, B11.x);
        }
    }

    // --- write dot products to smem ---
    {
        const int r = m0 + (lane >> 2);
        const int col = n0 + (lane & 3) * 2;
        char* v = sb + VS0;
        *(float2*)(v + r * VROWB + col * 4)        = make_float2(cH0[0] + cL0[0], cH0[1] + cL0[1]);
        *(float2*)(v + (r + 8) * VROWB + col * 4)  = make_float2(cH0[2] + cL0[2], cH0[3] + cL0[3]);
        *(float2*)(v + r * VROWB + (col + 8) * 4)       = make_float2(cH1[0] + cL1[0], cH1[1] + cL1[1]);
        *(float2*)(v + (r + 8) * VROWB + (col + 8) * 4) = make_float2(cH1[2] + cL1[2], cH1[3] + cL1[3]);
    }

    // reduce ||x||^2 across the 8-thread group sharing a row (lanes xor 1,2,4)
#pragma unroll
    for (int o = 1; o < 8; o <<= 1) xsq += __shfl_xor_sync(0xffffffffu, xsq, o);

    __syncthreads();

    // --- top-2 + softmax: token = tid/8, this thread scans experts xs*8..+7 ---
    {
        const int token = xrow;          // same mapping as X conversion
        const float xn = xsq;            // ||x_token||^2, already in-register
        const float* vr = (const float*)(sb + VS0 + token * VROWB) + xs * 8;
        float4 va = *(const float4*)vr;
        float4 vb = *(const float4*)(vr + 4);
        float dv[8] = {va.x, va.y, va.z, va.w, vb.x, vb.y, vb.z, vb.w};

        float m1 = 3.0e38f, m2 = 3.0e38f;
        int i1 = 0, i2 = 0;
#pragma unroll
        for (int i = 0; i < 8; i++) {
            int e = xs * 8 + i;
            float v = __ldg(&g_gn[e]) - 2.0f * dv[i];
            if (v < m1) { m2 = m1; i2 = i1; m1 = v; i1 = e; }
            else if (v < m2) { m2 = v; i2 = e; }
        }
        // merge top-2 across the 8-lane group (tie -> lower index)
#pragma unroll
        for (int o = 1; o < 8; o <<= 1) {
            float om1 = __shfl_xor_sync(0xffffffffu, m1, o);
            int   oi1 = __shfl_xor_sync(0xffffffffu, i1, o);
            float om2 = __shfl_xor_sync(0xffffffffu, m2, o);
            int   oi2 = __shfl_xor_sync(0xffffffffu, i2, o);
            bool of = (om1 < m1) || (om1 == m1 && oi1 < i1);
            if (of) {
                bool t = (m1 < om2) || (m1 == om2 && i1 < oi2);
                m2 = t ? m1 : om2; i2 = t ? i1 : oi2;
                m1 = om1; i1 = oi1;
            } else {
                bool t = (om1 < m2) || (om1 == m2 && oi1 < i2);
                m2 = t ? om1 : m2; i2 = t ? oi1 : i2;
            }
        }

        float l1 = -sqrtf(fmaxf(xn + m1, 0.f));
        float l2 = -sqrtf(fmaxf(xn + m2, 0.f));
        float w1 = 1.f / (1.f + expf(l2 - l1));  // l2 <= l1
        float w2 = 1.f - w1;

        float4* orow = (float4*)(out + (size_t)(t0 + token) * 64 + xs * 8);
        float4 o4;
        int e0 = xs * 8;
        o4.x = (e0 + 0 == i1) ? w1 : ((e0 + 0 == i2) ? w2 : 0.f);
        o4.y = (e0 + 1 == i1) ? w1 : ((e0 + 1 == i2) ? w2 : 0.f);
        o4.z = (e0 + 2 == i1) ? w1 : ((e0 + 2 == i2) ? w2 : 0.f);
        o4.w = (e0 + 3 == i1) ? w1 : ((e0 + 3 == i2) ? w2 : 0.f);
        orow[0] = o4;
        o4.x = (e0 + 4 == i1) ? w1 : ((e0 + 4 == i2) ? w2 : 0.f);
        o4.y = (e0 + 5 == i1) ? w1 : ((e0 + 5 == i2) ? w2 : 0.f);
        o4.z = (e0 + 6 == i1) ? w1 : ((e0 + 6 == i2) ? w2 : 0.f);
        o4.w = (e0 + 7 == i1) ? w1 : ((e0 + 7 == i2) ? w2 : 0.f);
        orow[1] = o4;
    }
}

// ---------------------------------------------------------------------------
extern "C" void kernel_launch(void* const* d_in, const int* in_sizes, int n_in,
                              void* d_out, int out_size) {
    const float* t1 = (const float*)d_in[0];
    const float* t2 = (const float*)d_in[1];
    const float* gw = (const float*)d_in[2];
    float* out = (float*)d_out;

    cudaFuncSetAttribute(gating_mma, cudaFuncAttributeMaxDynamicSharedMemorySize,
                         SMEM_BYTES);
    prep_kernel<<<NE, 256>>>(gw);
    gating_mma<<<NCTA, NT, SMEM_BYTES>>>(t1, t2, out);
}

// round 11
// speedup vs baseline: 1.3720x; 1.3720x over previous
#include <cuda_runtime.h>
#include <stdint.h>
#include <math.h>

#define NB 4096
#define NE 64
#define MT 32            // tokens per CTA
#define NCTA 128
#define NT 512
#define HCHUNK 16        // 64-wide K chunks per half (half = 1024)

// smem layout (relative to 1024-aligned base). Rows are 512B, XOR-swizzled.
#define XBUF 16384                     // 32 rows * 512B
#define GBUF 32768                     // 64 rows * 512B
#define XOFF(g, b) (((g) * 2 + (b)) * XBUF)           // 0 .. 65536
#define GOFF(g, b) (65536 + ((g) * 2 + (b)) * GBUF)   // .. 196608
#define XN_OFF 196608
#define GN_OFF 196864
#define SMEM_BYTES (197120 + 1024)
#define VPLANE 8704                    // 32 rows * 272B (reuses X region)
#define VROWB 272

// Scratch: swizzled hi/lo tf32 G image [chunk32][expert64][k'64], norm partials
__device__ uint2 g_g2[32 * 64 * 64];
__device__ float g_gnp[512];

static __device__ __forceinline__ int swz(int k, int row) {
    return k ^ ((k >> 3) & 6) ^ ((row & 1) << 3) ^ ((row & 2) << 1);
}
static __device__ __forceinline__ uint32_t f2tf(float x) {
    uint32_t r;
    asm("cvt.rna.tf32.f32 %0, %1;" : "=r"(r) : "f"(x));
    return r;
}
static __device__ __forceinline__ uint32_t s2u(const void* p) {
    uint32_t r;
    asm("{ .reg .u64 t; cvta.to.shared.u64 t, %1; cvt.u32.u64 %0, t; }"
        : "=r"(r) : "l"(p));
    return r;
}
static __device__ __forceinline__ void mma_tf32(float* c, uint32_t a0, uint32_t a1,
                                                uint32_t a2, uint32_t a3,
                                                uint32_t b0, uint32_t b1) {
    asm volatile(
        "mma.sync.aligned.m16n8k8.row.col.f32.tf32.tf32.f32 "
        "{%0,%1,%2,%3}, {%4,%5,%6,%7}, {%8,%9}, {%0,%1,%2,%3};"
        : "+f"(c[0]), "+f"(c[1]), "+f"(c[2]), "+f"(c[3])
        : "r"(a0), "r"(a1), "r"(a2), "r"(a3), "r"(b0), "r"(b1));
}
#define CP16(dst, src) \
    asm volatile("cp.async.cg.shared.global [%0], [%1], 16;" \
                 :: "r"(dst), "l"(src) : "memory")
#define CPCOMMIT() asm volatile("cp.async.commit_group;" ::: "memory")
#define CPWAIT0()  asm volatile("cp.async.wait_group 0;" ::: "memory")
#define GBAR(id) \
    asm volatile("bar.sync %0, %1;" :: "r"(id), "r"(256) : "memory")

// ---------------------------------------------------------------------------
// Prep: split G into tf32 hi/lo, write the swizzled smem image + norm partials.
// grid 512 (e = b>>3, part p = b&7), 256 threads, 1 element each.
// ---------------------------------------------------------------------------
__global__ __launch_bounds__(256) void prep_kernel(const float* __restrict__ gw) {
    const int e = blockIdx.x >> 3;
    const int p = blockIdx.x & 7;
    const int t = threadIdx.x;
    const int k = p * 256 + t;
    float v = gw[e * 2048 + k];
    uint32_t h = f2tf(v);
    uint32_t l = f2tf(v - __uint_as_float(h));
    const int c = k >> 6, kk = k & 63;
    g_g2[(c * 64 + e) * 64 + swz(kk, e)] = make_uint2(h, l);

    float s = v * v;
#pragma unroll
    for (int o = 16; o; o >>= 1) s += __shfl_xor_sync(0xffffffffu, s, o);
    __shared__ float red[8];
    if ((t & 31) == 0) red[t >> 5] = s;
    __syncthreads();
    if (t == 0) {
        float a = 0.f;
#pragma unroll
        for (int i = 0; i < 8; i++) a += red[i];
        g_gnp[blockIdx.x] = a;
    }
}

// ---------------------------------------------------------------------------
// Fused GEMM (tf32 mma.sync hi/lo split) + top-2 softmax scatter.
// 128 CTAs x 512 threads. Two independent 256-thread K-half groups.
// ---------------------------------------------------------------------------
__global__ __launch_bounds__(NT, 1)
void gating_mma(const float* __restrict__ t1, const float* __restrict__ t2,
                float* __restrict__ out) {
    extern __shared__ char sraw[];
    const uint32_t raw32 = s2u(sraw);
    const uint32_t base32 = (raw32 + 1023u) & ~1023u;
    char* sb = sraw + (base32 - raw32);

    const int tid = threadIdx.x;
    const int w = tid >> 5, lane = tid & 31;
    const int g = w >> 3, w8 = w & 7;
    const int mg = w8 >> 2, ng = (w8 >> 1) & 1, kg = w8 & 1;
    const int gtid = tid & 255;
    const int row = gtid >> 3, s = gtid & 7;     // X convert role
    const int t0 = blockIdx.x * MT;
    const float* xsrc = g ? t2 : t1;

    float* gn_s = (float*)(sb + GN_OFF);
    float* xn_s = (float*)(sb + XN_OFF);
    if (tid < 64) {
        float a = 0.f;
#pragma unroll
        for (int i = 0; i < 8; i++) a += g_gnp[tid * 8 + i];
        gn_s[tid] = a;
    }

    float C[4][4];
#pragma unroll
    for (int j = 0; j < 4; j++)
#pragma unroll
        for (int i = 0; i < 4; i++) C[j][i] = 0.f;
    float xsq = 0.f;

    // prologue: X chunk 0 regs + G chunk 0 cp.async
    float4 xv0, xv1;
    {
        const float4* xp = (const float4*)xsrc;
        size_t bidx = (size_t)(t0 + row) * 256 + s * 2;
        xv0 = xp[bidx];
        xv1 = xp[bidx + 1];
        uint32_t gd = base32 + GOFF(g, 0) + gtid * 128;
        const char* gs = (const char*)g_g2 + (size_t)(g * HCHUNK) * 32768 + gtid * 128;
#pragma unroll
        for (int i = 0; i < 8; i++) CP16(gd + i * 16, gs + i * 16);
        CPCOMMIT();
    }

    const int rm = (((lane >> 2) & 1) << 3) | (((lane >> 2) & 2) << 1);
    const int cc = lane & 3;

    for (int c = 0; c < HCHUNK; c++) {
        const int b = c & 1;
        char* xb = sb + XOFF(g, b);

        // convert + STS X (hi/lo tf32, swizzled), accumulate ||x||^2
        {
            float v[8] = {xv0.x, xv0.y, xv0.z, xv0.w, xv1.x, xv1.y, xv1.z, xv1.w};
#pragma unroll
            for (int j = 0; j < 4; j++) {
                float v0 = v[2 * j], v1 = v[2 * j + 1];
                xsq += v0 * v0 + v1 * v1;
                uint32_t h0 = f2tf(v0), h1 = f2tf(v1);
                uint32_t l0 = f2tf(v0 - __uint_as_float(h0));
                uint32_t l1 = f2tf(v1 - __uint_as_float(h1));
                int kp = swz(s * 8 + 2 * j, row);
                *(uint4*)(xb + row * 512 + kp * 8) = make_uint4(h0, l0, h1, l1);
            }
        }

        CPWAIT0();
        GBAR(1 + g);

        // prefetch next chunk (hides DRAM/L2 latency under the MMAs below)
        if (c + 1 < HCHUNK) {
            const float4* xp = (const float4*)xsrc;
            size_t bidx = (size_t)(t0 + row) * 256 + (c + 1) * 16 + s * 2;
            xv0 = xp[bidx];
            xv1 = xp[bidx + 1];
            uint32_t gd = base32 + GOFF(g, b ^ 1) + gtid * 128;
            const char* gs = (const char*)g_g2 +
                             (size_t)(g * HCHUNK + c + 1) * 32768 + gtid * 128;
#pragma unroll
            for (int i = 0; i < 8; i++) CP16(gd + i * 16, gs + i * 16);
            CPCOMMIT();
        }

        // MMA: warp tile m16 x n32, ks-half kg (4 of 8 k-steps)
        const char* Xr = sb + XOFF(g, b) + (mg * 16 + (lane >> 2)) * 512;
        const char* Gb = sb + GOFF(g, b) + (ng * 32 + (lane >> 2)) * 512;
#pragma unroll
        for (int u = 0; u < 4; u++) {
            int ksG = kg * 4 + u;
            int o0 = ((ksG * 8 + cc) ^ (ksG & 6) ^ rm) * 8;
            int o2 = o0 ^ 32;
            uint2 A0 = *(const uint2*)(Xr + o0);
            uint2 A1 = *(const uint2*)(Xr + o0 + 4096);
            uint2 A2 = *(const uint2*)(Xr + o2);
            uint2 A3 = *(const uint2*)(Xr + o2 + 4096);
#pragma unroll
            for (int j = 0; j < 4; j++) {
                const char* Bp = Gb + j * 4096;
                uint2 B0 = *(const uint2*)(Bp + o0);
                uint2 B1 = *(const uint2*)(Bp + o2);
                mma_tf32(C[j], A0.x, A1.x, A2.x, A3.x, B0.x, B1.x);  // hi*hi
                mma_tf32(C[j], A0.x, A1.x, A2.x, A3.x, B0.y, B1.y);  // hi*lo
                mma_tf32(C[j], A0.y, A1.y, A2.y, A3.y, B0.x, B1.x);  // lo*hi
            }
        }
    }

    // ||x||^2 partial: sum the 8 threads sharing a row, store per K-half
#pragma unroll
    for (int o = 1; o < 8; o <<= 1) xsq += __shfl_xor_sync(0xffffffffu, xsq, o);
    if (s == 0) xn_s[g * 32 + row] = xsq;

    __syncthreads();   // all MMAs done; X region now reusable for V planes

    // store C fragments into V plane p = g*2+kg (partial sums over K/ks halves)
    {
        char* vp = sb + (g * 2 + kg) * VPLANE;
        const int ra = mg * 16 + (lane >> 2);
        const int cb = ng * 32 + (lane & 3) * 2;
#pragma unroll
        for (int j = 0; j < 4; j++) {
            int col = cb + j * 8;
            *(float2*)(vp + ra * VROWB + col * 4) = make_float2(C[j][0], C[j][1]);
            *(float2*)(vp + (ra + 8) * VROWB + col * 4) = make_float2(C[j][2], C[j][3]);
        }
    }
    __syncthreads();

    // epilogue: token = tid>>3, this thread scans experts s2*8..+7
    if (tid < 256) {
        const int token = tid >> 3;
        const int s2 = tid & 7;
        float dv[8];
        {
            float4 a0 = make_float4(0.f, 0.f, 0.f, 0.f), a1 = a0;
#pragma unroll
            for (int p = 0; p < 4; p++) {
                const char* vp = sb + p * VPLANE + token * VROWB + s2 * 32;
                float4 q0 = *(const float4*)vp;
                float4 q1 = *(const float4*)(vp + 16);
                a0.x += q0.x; a0.y += q0.y; a0.z += q0.z; a0.w += q0.w;
                a1.x += q1.x; a1.y += q1.y; a1.z += q1.z; a1.w += q1.w;
            }
            dv[0] = a0.x; dv[1] = a0.y; dv[2] = a0.z; dv[3] = a0.w;
            dv[4] = a1.x; dv[5] = a1.y; dv[6] = a1.z; dv[7] = a1.w;
        }
        const float xn = xn_s[token] + xn_s[32 + token];

        float m1 = 3.0e38f, m2 = 3.0e38f;
        int i1 = 0, i2 = 0;
#pragma unroll
        for (int i = 0; i < 8; i++) {
            int e = s2 * 8 + i;
            float v = gn_s[e] - 2.0f * dv[i];
            if (v < m1) { m2 = m1; i2 = i1; m1 = v; i1 = e; }
            else if (v < m2) { m2 = v; i2 = e; }
        }
        // merge top-2 across the 8-lane group (tie -> lower index)
#pragma unroll
        for (int o = 1; o < 8; o <<= 1) {
            float om1 = __shfl_xor_sync(0xffffffffu, m1, o);
            int   oi1 = __shfl_xor_sync(0xffffffffu, i1, o);
            float om2 = __shfl_xor_sync(0xffffffffu, m2, o);
            int   oi2 = __shfl_xor_sync(0xffffffffu, i2, o);
            bool of = (om1 < m1) || (om1 == m1 && oi1 < i1);
            if (of) {
                bool t = (m1 < om2) || (m1 == om2 && i1 < oi2);
                m2 = t ? m1 : om2; i2 = t ? i1 : oi2;
                m1 = om1; i1 = oi1;
            } else {
                bool t = (om1 < m2) || (om1 == m2 && oi1 < i2);
                m2 = t ? om1 : m2; i2 = t ? oi1 : i2;
            }
        }

        float l1 = -sqrtf(fmaxf(xn + m1, 0.f));
        float l2 = -sqrtf(fmaxf(xn + m2, 0.f));
        float w1 = 1.f / (1.f + expf(l2 - l1));  // l2 <= l1
        float w2 = 1.f - w1;

        float4* orow = (float4*)(out + (size_t)(t0 + token) * 64 + s2 * 8);
        int e0 = s2 * 8;
        float4 o4;
        o4.x = (e0 + 0 == i1) ? w1 : ((e0 + 0 == i2) ? w2 : 0.f);
        o4.y = (e0 + 1 == i1) ? w1 : ((e0 + 1 == i2) ? w2 : 0.f);
        o4.z = (e0 + 2 == i1) ? w1 : ((e0 + 2 == i2) ? w2 : 0.f);
        o4.w = (e0 + 3 == i1) ? w1 : ((e0 + 3 == i2) ? w2 : 0.f);
        orow[0] = o4;
        o4.x = (e0 + 4 == i1) ? w1 : ((e0 + 4 == i2) ? w2 : 0.f);
        o4.y = (e0 + 5 == i1) ? w1 : ((e0 + 5 == i2) ? w2 : 0.f);
        o4.z = (e0 + 6 == i1) ? w1 : ((e0 + 6 == i2) ? w2 : 0.f);
        o4.w = (e0 + 7 == i1) ? w1 : ((e0 + 7 == i2) ? w2 : 0.f);
        orow[1] = o4;
    }
}

// ---------------------------------------------------------------------------
extern "C" void kernel_launch(void* const* d_in, const int* in_sizes, int n_in,
                              void* d_out, int out_size) {
    const float* t1 = (const float*)d_in[0];
    const float* t2 = (const float*)d_in[1];
    const float* gw = (const float*)d_in[2];
    float* out = (float*)d_out;

    cudaFuncSetAttribute(gating_mma, cudaFuncAttributeMaxDynamicSharedMemorySize,
                         SMEM_BYTES);
    prep_kernel<<<512, 256>>>(gw);
    gating_mma<<<NCTA, NT, SMEM_BYTES>>>(t1, t2, out);
}